// round 15
// baseline (speedup 1.0000x reference)
#include <cuda_runtime.h>
#include <cuda_fp16.h>
#include <cstdint>

// ---------------------------------------------------------------------------
// SSMDecoder: ys = 2*Re( scan(exp(L*dt), x@B_bar^T) @ C^T ) + D*x
// Bsz=8, L=4096, H=512, P=256 (complex state as re/im planes, N2=512).
// GEMMs: mma.sync m16n8k16 fp16 single-pass, cp.async 6-stage pipeline,
// 512 threads/CTA (16 warps of 32x32) for 8 warps/SMSP at 2 CTAs/SM.
// ---------------------------------------------------------------------------

#define BSZ 8
#define LEN 4096
#define HH  512
#define PP  256
#define N2  512
#define MT  (BSZ*LEN)           // 32768
#define CHUNK 64
#define NCHUNK (LEN/CHUNK)      // 64
#define KT  512
#define NT  512

typedef __half fp16;

// ------------------------------- scratch -----------------------------------
__device__ __align__(16) fp16 g_Buh[(size_t)MT * N2];      // 32 MB (Bu fp16)
__device__ __align__(16) fp16 g_xf[(size_t)MT * N2];       // 32 MB (x  fp16)
__device__ __align__(16) fp16 g_Xf[(size_t)MT * N2];       // 32 MB (xs fp16)
__device__ __align__(16) fp16 g_G1f[N2 * HH];
__device__ __align__(16) fp16 g_G2f[HH * N2];
__device__ float g_lam[2 * PP];
__device__ float g_f[2 * PP];
__device__ float g_pow[(CHUNK + 1) * N2];
__device__ float g_cs[BSZ * NCHUNK * N2];
__device__ float g_carry[BSZ * NCHUNK * N2];

// ------------------------------ helpers ------------------------------------
__device__ __forceinline__ uint32_t smem_u32(const void* p) {
    uint32_t a;
    asm("{ .reg .u64 t; cvta.to.shared.u64 t, %1; cvt.u32.u64 %0, t; }"
        : "=r"(a) : "l"(p));
    return a;
}
__device__ __forceinline__ void ldsm4(uint32_t* r, uint32_t addr) {
    asm volatile("ldmatrix.sync.aligned.m8n8.x4.shared.b16 {%0,%1,%2,%3}, [%4];"
                 : "=r"(r[0]), "=r"(r[1]), "=r"(r[2]), "=r"(r[3]) : "r"(addr));
}
__device__ __forceinline__ void mma_f16(float* c, const uint32_t* a, const uint32_t* b) {
    asm volatile(
        "mma.sync.aligned.m16n8k16.row.col.f32.f16.f16.f32 "
        "{%0,%1,%2,%3}, {%4,%5,%6,%7}, {%8,%9}, {%0,%1,%2,%3};"
        : "+f"(c[0]), "+f"(c[1]), "+f"(c[2]), "+f"(c[3])
        : "r"(a[0]), "r"(a[1]), "r"(a[2]), "r"(a[3]), "r"(b[0]), "r"(b[1]));
}
__device__ __forceinline__ uint32_t packh(float x, float y) {
    __half2 t = __floats2half2_rn(x, y);
    return *reinterpret_cast<uint32_t*>(&t);
}
#define CP16(dst, src) \
    asm volatile("cp.async.cg.shared.global [%0], [%1], 16;" :: "r"(dst), "l"(src) : "memory")
#define CP_COMMIT asm volatile("cp.async.commit_group;" ::: "memory")
#define CP_WAIT(n) asm volatile("cp.async.wait_group %0;" :: "n"(n) : "memory")

// ------------------------------- setup -------------------------------------
__global__ void k_setup(const float* __restrict__ lre,
                        const float* __restrict__ lim,
                        const float* __restrict__ lstep) {
    int p = threadIdx.x;
    if (p >= PP) return;
    float st = expf(lstep[p]);
    float ar = lre[p], ai = lim[p];
    float e  = expf(ar * st);
    float th = ai * st;
    float lr = e * cosf(th), li = e * sinf(th);
    g_lam[p] = lr; g_lam[PP + p] = li;
    float nr = lr - 1.0f, ni = li;
    float den = ar * ar + ai * ai;
    g_f[p]      = (nr * ar + ni * ai) / den;
    g_f[PP + p] = (ni * ar - nr * ai) / den;
    float pr = 1.0f, pi = 0.0f;
    for (int k = 0; k <= CHUNK; k++) {
        g_pow[k * N2 + p]      = pr;
        g_pow[k * N2 + PP + p] = pi;
        float t = pr * lr - pi * li;
        pi = pr * li + pi * lr;
        pr = t;
    }
}

__global__ void k_fill(const float* __restrict__ Bm, const float* __restrict__ Cm) {
    int tid = blockIdx.x * blockDim.x + threadIdx.x;
    if (tid >= N2 * HH) return;
    {   // G1[n][h]
        int n = tid / HH, h = tid - n * HH;
        int p = n & (PP - 1);
        float fr = g_f[p], fi = g_f[PP + p];
        float b0 = Bm[(p * HH + h) * 2], b1 = Bm[(p * HH + h) * 2 + 1];
        float v = (n < PP) ? (fr * b0 - fi * b1) : (fr * b1 + fi * b0);
        g_G1f[tid] = __float2half_rn(v);
    }
    {   // G2[h][n]
        int h = tid / N2, n = tid - h * N2;
        float v;
        if (n < PP) v =  2.0f * Cm[(h * PP + n) * 2];
        else        v = -2.0f * Cm[(h * PP + (n - PP)) * 2 + 1];
        g_G2f[tid] = __float2half_rn(v);
    }
}

// x -> fp16 plane (one shot)
__global__ void k_xconv(const float* __restrict__ x) {
    size_t i4 = (size_t)blockIdx.x * blockDim.x + threadIdx.x;
    float4 v = *(const float4*)(x + i4 * 4);
    uint2 hp = make_uint2(packh(v.x, v.y), packh(v.z, v.w));
    *(uint2*)(g_xf + i4 * 4) = hp;
}

// --------------------------- mma.sync GEMM ---------------------------------
// CTA 128x128, K-chunk 16, 512 threads = 16 warps (4M x 4N), warp 32x32.
// SMEM: 6 stages x 2 fp16 planes (A, B), rows padded to 24 halves.

#define AROW  24
#define PLANE (128 * AROW * 2)          // 6144 B
#define STAGE (2 * PLANE)               // 12288 B
#define NSTG  6
#define GSMEM (NSTG * STAGE)            // 73728 B

template <bool EPI, bool HOUT>
__device__ __forceinline__ void gemm_mma(const fp16* __restrict__ Af,
                                         const fp16* __restrict__ Bf,
                                         void* __restrict__ Cg,
                                         const float* __restrict__ Xg,
                                         const float* __restrict__ Dg) {
    extern __shared__ __align__(16) char smem[];
    const uint32_t sb = smem_u32(smem);
    const int tid = threadIdx.x;
    const int wid = tid >> 5;
    const int l   = tid & 31;
    const int warp_m = wid >> 2;        // 0..3 -> M offset *32
    const int warp_n = wid & 3;         // 0..3 -> N offset *32
    const int rowBase = blockIdx.y * 128;
    const int colBase = blockIdx.x * 128;

    // cp.async: 1 op/thread/kt. tid<256 -> A plane, else B plane.
    const int rowA  = (tid >> 1) & 127;
    const int chunk = tid & 1;
    const bool isB  = tid >= 256;
    const fp16* sp = isB ? (Bf + (size_t)(colBase + rowA) * KT + chunk * 8)
                         : (Af + (size_t)(rowBase + rowA) * KT + chunk * 8);
    const uint32_t dA = sb + (isB ? PLANE : 0) + rowA * (AROW * 2) + chunk * 16;

#define ISSUE(stg, kt) CP16(dA + (stg) * STAGE, sp + (size_t)(kt) * 16)

    float acc[2][4][4];
#pragma unroll
    for (int i = 0; i < 2; i++)
#pragma unroll
        for (int j = 0; j < 4; j++)
#pragma unroll
            for (int k = 0; k < 4; k++) acc[i][j][k] = 0.0f;

    ISSUE(0, 0); CP_COMMIT;
    ISSUE(1, 1); CP_COMMIT;
    ISSUE(2, 2); CP_COMMIT;
    ISSUE(3, 3); CP_COMMIT;
    ISSUE(4, 4); CP_COMMIT;

    const int a_row = l & 15;
    const int a_k   = (l >> 4) * 8;
    const int b_row = (l & 7) + ((l >> 4) << 3);
    const int b_k   = ((l >> 3) & 1) * 8;
    const uint32_t aoff = (uint32_t)(((warp_m * 32 + a_row) * AROW + a_k) * 2);
    const uint32_t boff = (uint32_t)(((warp_n * 32 + b_row) * AROW + b_k) * 2);

    int stg = 0, pstg = 5;
    for (int kt = 0; kt < 32; kt++) {
        CP_WAIT(4);
        __syncthreads();
        if (kt + 5 < 32) ISSUE(pstg, kt + 5);
        CP_COMMIT;
        if (++pstg == NSTG) pstg = 0;

        const uint32_t base = sb + stg * STAGE;
        if (++stg == NSTG) stg = 0;

        uint32_t bR[2][4];
#pragma unroll
        for (int nb = 0; nb < 2; nb++)
            ldsm4(bR[nb], base + PLANE + boff + (uint32_t)(nb * 16 * AROW * 2));
#pragma unroll
        for (int mt = 0; mt < 2; mt++) {
            uint32_t aR[4];
            ldsm4(aR, base + aoff + (uint32_t)(mt * 16 * AROW * 2));
#pragma unroll
            for (int nt = 0; nt < 4; nt++)
                mma_f16(acc[mt][nt], aR, &bR[nt >> 1][(nt & 1) * 2]);
        }
    }
#undef ISSUE

    // ---- epilogue ----
    const int r0 = l >> 2;
    const int cp = (l & 3) * 2;
#pragma unroll
    for (int mt = 0; mt < 2; mt++) {
#pragma unroll
        for (int nt = 0; nt < 4; nt++) {
            const int row = rowBase + warp_m * 32 + mt * 16 + r0;
            const int col = colBase + warp_n * 32 + nt * 8 + cp;
            float2 v0 = make_float2(acc[mt][nt][0], acc[mt][nt][1]);
            float2 v1 = make_float2(acc[mt][nt][2], acc[mt][nt][3]);
            size_t o0 = (size_t)row * NT + col;
            size_t o1 = (size_t)(row + 8) * NT + col;
            if (HOUT) {
                fp16* C = (fp16*)Cg;
                *(uint32_t*)(C + o0) = packh(v0.x, v0.y);
                *(uint32_t*)(C + o1) = packh(v1.x, v1.y);
            } else {
                float* C = (float*)Cg;
                if (EPI) {
                    float2 d  = *(const float2*)(Dg + col);
                    float2 x0 = *(const float2*)(Xg + o0);
                    float2 x1 = *(const float2*)(Xg + o1);
                    v0.x += d.x * x0.x; v0.y += d.y * x0.y;
                    v1.x += d.x * x1.x; v1.y += d.y * x1.y;
                }
                *(float2*)(C + o0) = v0;
                *(float2*)(C + o1) = v1;
            }
        }
    }
}

__global__ __launch_bounds__(512, 2) void k_gemm1() {
    gemm_mma<false, true>(g_xf, g_G1f, g_Buh, nullptr, nullptr);
}
__global__ __launch_bounds__(512, 2) void k_gemm2(const float* __restrict__ x,
                                                  const float* __restrict__ D,
                                                  float* __restrict__ out) {
    gemm_mma<true, false>(g_Xf, g_G2f, out, x, D);
}

// ------------------------------- scan --------------------------------------
// Pass 1: chunk sums only (read Bu fp16 once, write tiny cs).
__global__ void k_sums() {
    const int b = blockIdx.x >> 6;
    const int c = blockIdx.x & 63;
    const int p = threadIdx.x;
    const float lr = g_lam[p], li = g_lam[PP + p];
    float sr = 0.0f, si = 0.0f;
    size_t base = (size_t)(b * LEN + c * CHUNK) * N2;
#pragma unroll 4
    for (int j = 0; j < CHUNK; j++) {
        size_t o = base + (size_t)j * N2;
        float ur = __half2float(g_Buh[o + p]);
        float ui = __half2float(g_Buh[o + PP + p]);
        float nr = fmaf(lr, sr, fmaf(-li, si, ur));
        float ni = fmaf(lr, si, fmaf(li, sr, ui));
        sr = nr; si = ni;
    }
    int co = (b * NCHUNK + c) * N2;
    g_cs[co + p] = sr;
    g_cs[co + PP + p] = si;
}

// Pass 2: scan of chunk sums with multiplier lam^64 -> carries.
__global__ void k_chunkscan() {
    const int b = blockIdx.x;
    const int p = threadIdx.x;
    const float tr = g_pow[CHUNK * N2 + p], ti = g_pow[CHUNK * N2 + PP + p];
    float sr = 0.0f, si = 0.0f;
#pragma unroll 4
    for (int c = 0; c < NCHUNK; c++) {
        int o = (b * NCHUNK + c) * N2;
        g_carry[o + p] = sr;
        g_carry[o + PP + p] = si;
        float cr = g_cs[o + p], ci = g_cs[o + PP + p];
        float nr = fmaf(tr, sr, fmaf(-ti, si, cr));
        float ni = fmaf(tr, si, fmaf(ti, sr, ci));
        sr = nr; si = ni;
    }
}

// Pass 3: local scan seeded with carry, write xs directly as fp16.
__global__ void k_scanapply() {
    const int b = blockIdx.x >> 6;
    const int c = blockIdx.x & 63;
    const int p = threadIdx.x;
    const float lr = g_lam[p], li = g_lam[PP + p];
    const int co = (b * NCHUNK + c) * N2;
    float sr = (c == 0) ? 0.0f : g_carry[co + p];
    float si = (c == 0) ? 0.0f : g_carry[co + PP + p];
    size_t base = (size_t)(b * LEN + c * CHUNK) * N2;
#pragma unroll 4
    for (int j = 0; j < CHUNK; j++) {
        size_t o = base + (size_t)j * N2;
        float ur = __half2float(g_Buh[o + p]);
        float ui = __half2float(g_Buh[o + PP + p]);
        float nr = fmaf(lr, sr, fmaf(-li, si, ur));
        float ni = fmaf(lr, si, fmaf(li, sr, ui));
        g_Xf[o + p]      = __float2half_rn(nr);
        g_Xf[o + PP + p] = __float2half_rn(ni);
        sr = nr; si = ni;
    }
}

// ------------------------------ launcher -----------------------------------
extern "C" void kernel_launch(void* const* d_in, const int* in_sizes, int n_in,
                              void* d_out, int out_size) {
    (void)in_sizes; (void)n_in; (void)out_size;
    const float* x     = (const float*)d_in[0];
    const float* lre   = (const float*)d_in[1];
    const float* lim   = (const float*)d_in[2];
    const float* Bm    = (const float*)d_in[3];
    const float* Cm    = (const float*)d_in[4];
    const float* D     = (const float*)d_in[5];
    const float* lstep = (const float*)d_in[6];
    float* out = (float*)d_out;

    cudaFuncSetAttribute(k_gemm1, cudaFuncAttributeMaxDynamicSharedMemorySize, GSMEM);
    cudaFuncSetAttribute(k_gemm2, cudaFuncAttributeMaxDynamicSharedMemorySize, GSMEM);

    k_setup<<<1, 256>>>(lre, lim, lstep);
    k_fill<<<(N2 * HH + 255) / 256, 256>>>(Bm, Cm);
    k_xconv<<<(MT * N2 / 4) / 256, 256>>>(x);

    dim3 gg(NT / 128, MT / 128);  // (4, 256)
    k_gemm1<<<gg, 512, GSMEM>>>();
    k_sums<<<BSZ * NCHUNK, 256>>>();
    k_chunkscan<<<BSZ, 256>>>();
    k_scanapply<<<BSZ * NCHUNK, 256>>>();
    k_gemm2<<<gg, 512, GSMEM>>>(x, D, out);
}

// round 16
// speedup vs baseline: 1.1063x; 1.1063x over previous
#include <cuda_runtime.h>
#include <cuda_fp16.h>
#include <cstdint>

// ---------------------------------------------------------------------------
// SSMDecoder: ys = 2*Re( scan(exp(L*dt), x@B_bar^T) @ C^T ) + D*x
// Bsz=8, L=4096, H=512, P=256 (complex state as re/im planes, N2=512).
// GEMMs: mma.sync m16n8k16 fp16 single-pass, cp.async 4-stage pipeline,
// K-chunk 32 (16 iterations; halved barrier count vs K-chunk 16).
// 256 threads/CTA, 8 warps of 64x32, 2 CTAs/SM.
// ---------------------------------------------------------------------------

#define BSZ 8
#define LEN 4096
#define HH  512
#define PP  256
#define N2  512
#define MT  (BSZ*LEN)           // 32768
#define CHUNK 64
#define NCHUNK (LEN/CHUNK)      // 64
#define KT  512
#define NT  512

typedef __half fp16;

// ------------------------------- scratch -----------------------------------
__device__ __align__(16) fp16 g_Buh[(size_t)MT * N2];      // 32 MB (Bu fp16)
__device__ __align__(16) fp16 g_xf[(size_t)MT * N2];       // 32 MB (x  fp16)
__device__ __align__(16) fp16 g_Xf[(size_t)MT * N2];       // 32 MB (xs fp16)
__device__ __align__(16) fp16 g_G1f[N2 * HH];
__device__ __align__(16) fp16 g_G2f[HH * N2];
__device__ float g_lam[2 * PP];
__device__ float g_f[2 * PP];
__device__ float g_pow[(CHUNK + 1) * N2];
__device__ float g_cs[BSZ * NCHUNK * N2];
__device__ float g_carry[BSZ * NCHUNK * N2];

// ------------------------------ helpers ------------------------------------
__device__ __forceinline__ uint32_t smem_u32(const void* p) {
    uint32_t a;
    asm("{ .reg .u64 t; cvta.to.shared.u64 t, %1; cvt.u32.u64 %0, t; }"
        : "=r"(a) : "l"(p));
    return a;
}
__device__ __forceinline__ void ldsm4(uint32_t* r, uint32_t addr) {
    asm volatile("ldmatrix.sync.aligned.m8n8.x4.shared.b16 {%0,%1,%2,%3}, [%4];"
                 : "=r"(r[0]), "=r"(r[1]), "=r"(r[2]), "=r"(r[3]) : "r"(addr));
}
__device__ __forceinline__ void mma_f16(float* c, const uint32_t* a, const uint32_t* b) {
    asm volatile(
        "mma.sync.aligned.m16n8k16.row.col.f32.f16.f16.f32 "
        "{%0,%1,%2,%3}, {%4,%5,%6,%7}, {%8,%9}, {%0,%1,%2,%3};"
        : "+f"(c[0]), "+f"(c[1]), "+f"(c[2]), "+f"(c[3])
        : "r"(a[0]), "r"(a[1]), "r"(a[2]), "r"(a[3]), "r"(b[0]), "r"(b[1]));
}
__device__ __forceinline__ uint32_t packh(float x, float y) {
    __half2 t = __floats2half2_rn(x, y);
    return *reinterpret_cast<uint32_t*>(&t);
}
#define CP16(dst, src) \
    asm volatile("cp.async.cg.shared.global [%0], [%1], 16;" :: "r"(dst), "l"(src) : "memory")
#define CP_COMMIT asm volatile("cp.async.commit_group;" ::: "memory")
#define CP_WAIT(n) asm volatile("cp.async.wait_group %0;" :: "n"(n) : "memory")

// ------------------------------- setup -------------------------------------
__global__ void k_setup(const float* __restrict__ lre,
                        const float* __restrict__ lim,
                        const float* __restrict__ lstep) {
    int p = threadIdx.x;
    if (p >= PP) return;
    float st = expf(lstep[p]);
    float ar = lre[p], ai = lim[p];
    float e  = expf(ar * st);
    float th = ai * st;
    float lr = e * cosf(th), li = e * sinf(th);
    g_lam[p] = lr; g_lam[PP + p] = li;
    float nr = lr - 1.0f, ni = li;
    float den = ar * ar + ai * ai;
    g_f[p]      = (nr * ar + ni * ai) / den;
    g_f[PP + p] = (ni * ar - nr * ai) / den;
    float pr = 1.0f, pi = 0.0f;
    for (int k = 0; k <= CHUNK; k++) {
        g_pow[k * N2 + p]      = pr;
        g_pow[k * N2 + PP + p] = pi;
        float t = pr * lr - pi * li;
        pi = pr * li + pi * lr;
        pr = t;
    }
}

__global__ void k_fill(const float* __restrict__ Bm, const float* __restrict__ Cm) {
    int tid = blockIdx.x * blockDim.x + threadIdx.x;
    if (tid >= N2 * HH) return;
    {   // G1[n][h]
        int n = tid / HH, h = tid - n * HH;
        int p = n & (PP - 1);
        float fr = g_f[p], fi = g_f[PP + p];
        float b0 = Bm[(p * HH + h) * 2], b1 = Bm[(p * HH + h) * 2 + 1];
        float v = (n < PP) ? (fr * b0 - fi * b1) : (fr * b1 + fi * b0);
        g_G1f[tid] = __float2half_rn(v);
    }
    {   // G2[h][n]
        int h = tid / N2, n = tid - h * N2;
        float v;
        if (n < PP) v =  2.0f * Cm[(h * PP + n) * 2];
        else        v = -2.0f * Cm[(h * PP + (n - PP)) * 2 + 1];
        g_G2f[tid] = __float2half_rn(v);
    }
}

// x -> fp16 plane (one shot)
__global__ void k_xconv(const float* __restrict__ x) {
    size_t i4 = (size_t)blockIdx.x * blockDim.x + threadIdx.x;
    float4 v = *(const float4*)(x + i4 * 4);
    uint2 hp = make_uint2(packh(v.x, v.y), packh(v.z, v.w));
    *(uint2*)(g_xf + i4 * 4) = hp;
}

// --------------------------- mma.sync GEMM ---------------------------------
// CTA 128x128, K-chunk 32, 256 threads = 8 warps (2M x 4N), warp 64x32.
// SMEM: 4 stages x 2 fp16 planes (A, B), rows padded to 40 halves (80 B,
// conflict-free for ldmatrix.x4: 8 row addrs hit 8 distinct 16B banks).

#define KCH   32
#define NKT   (KT / KCH)                // 16
#define AROW  40
#define PLANE (128 * AROW * 2)          // 10240 B
#define STAGE (2 * PLANE)               // 20480 B
#define NSTG  4
#define GSMEM (NSTG * STAGE)            // 81920 B

template <bool EPI, bool HOUT>
__device__ __forceinline__ void gemm_mma(const fp16* __restrict__ Af,
                                         const fp16* __restrict__ Bf,
                                         void* __restrict__ Cg,
                                         const fp16* __restrict__ Xh,
                                         const float* __restrict__ Dg) {
    extern __shared__ __align__(16) char smem[];
    const uint32_t sb = smem_u32(smem);
    const int tid = threadIdx.x;
    const int wid = tid >> 5;
    const int l   = tid & 31;
    const int warp_m = wid >> 2;        // 0..1 -> M offset *64
    const int warp_n = wid & 3;         // 0..3 -> N offset *32
    const int rowBase = blockIdx.y * 128;
    const int colBase = blockIdx.x * 128;

    // cp.async mapping: 1024 16B-ops per stage (2 planes x 128 rows x 4 chunks),
    // 4 per thread: idx = tid + 256*i; plane = idx>=512; r = (idx&511)>>2; c = idx&3.
    const int i0 = tid;                 // A rows (tid < 512 always for i=0,1)
    // Precompute per-i source pointers and smem offsets.
    const fp16* srcs[4];
    uint32_t dsts[4];
#pragma unroll
    for (int i = 0; i < 4; i++) {
        int idx = tid + 256 * i;
        int pl  = idx >> 9;             // 0 = A, 1 = B
        int r   = (idx & 511) >> 2;
        int c   = idx & 3;
        srcs[i] = (pl ? (Bf + (size_t)(colBase + r) * KT)
                      : (Af + (size_t)(rowBase + r) * KT)) + c * 8;
        dsts[i] = sb + pl * PLANE + r * (AROW * 2) + c * 16;
    }
    (void)i0;

#define ISSUE(stg, kt) do { \
    size_t ko_ = (size_t)(kt) * KCH; \
    uint32_t so_ = (stg) * STAGE; \
    CP16(dsts[0] + so_, srcs[0] + ko_); \
    CP16(dsts[1] + so_, srcs[1] + ko_); \
    CP16(dsts[2] + so_, srcs[2] + ko_); \
    CP16(dsts[3] + so_, srcs[3] + ko_); \
} while (0)

    float acc[4][4][4];
#pragma unroll
    for (int i = 0; i < 4; i++)
#pragma unroll
        for (int j = 0; j < 4; j++)
#pragma unroll
            for (int k = 0; k < 4; k++) acc[i][j][k] = 0.0f;

    ISSUE(0, 0); CP_COMMIT;
    ISSUE(1, 1); CP_COMMIT;
    ISSUE(2, 2); CP_COMMIT;

    const int a_row = l & 15;
    const int a_k   = (l >> 4) * 8;
    const int b_row = (l & 7) + ((l >> 4) << 3);
    const int b_k   = ((l >> 3) & 1) * 8;
    const uint32_t aoff = (uint32_t)(((warp_m * 64 + a_row) * AROW + a_k) * 2);
    const uint32_t boff = (uint32_t)(((warp_n * 32 + b_row) * AROW + b_k) * 2);

    int stg = 0, pstg = 3;
    for (int kt = 0; kt < NKT; kt++) {
        CP_WAIT(2);
        __syncthreads();
        if (kt + 3 < NKT) ISSUE(pstg, kt + 3);
        CP_COMMIT;
        if (++pstg == NSTG) pstg = 0;

        const uint32_t base = sb + stg * STAGE;
        if (++stg == NSTG) stg = 0;

#pragma unroll
        for (int kk = 0; kk < 2; kk++) {
            const uint32_t kof = (uint32_t)(kk * 16 * 2);   // 16 halves = 32 B
            uint32_t bR[2][4];
#pragma unroll
            for (int nb = 0; nb < 2; nb++)
                ldsm4(bR[nb], base + PLANE + boff + kof + (uint32_t)(nb * 16 * AROW * 2));
#pragma unroll
            for (int mt = 0; mt < 4; mt++) {
                uint32_t aR[4];
                ldsm4(aR, base + aoff + kof + (uint32_t)(mt * 16 * AROW * 2));
#pragma unroll
                for (int nt = 0; nt < 4; nt++)
                    mma_f16(acc[mt][nt], aR, &bR[nt >> 1][(nt & 1) * 2]);
            }
        }
    }
#undef ISSUE

    // ---- epilogue ----
    const int r0 = l >> 2;
    const int cp = (l & 3) * 2;
#pragma unroll
    for (int mt = 0; mt < 4; mt++) {
#pragma unroll
        for (int nt = 0; nt < 4; nt++) {
            const int row = rowBase + warp_m * 64 + mt * 16 + r0;
            const int col = colBase + warp_n * 32 + nt * 8 + cp;
            float2 v0 = make_float2(acc[mt][nt][0], acc[mt][nt][1]);
            float2 v1 = make_float2(acc[mt][nt][2], acc[mt][nt][3]);
            size_t o0 = (size_t)row * NT + col;
            size_t o1 = (size_t)(row + 8) * NT + col;
            if (HOUT) {
                fp16* C = (fp16*)Cg;
                *(uint32_t*)(C + o0) = packh(v0.x, v0.y);
                *(uint32_t*)(C + o1) = packh(v1.x, v1.y);
            } else {
                float* C = (float*)Cg;
                if (EPI) {
                    float2 d  = *(const float2*)(Dg + col);
                    __half2 xh0 = *(const __half2*)(Xh + o0);
                    __half2 xh1 = *(const __half2*)(Xh + o1);
                    float2 x0 = __half22float2(xh0);
                    float2 x1 = __half22float2(xh1);
                    v0.x += d.x * x0.x; v0.y += d.y * x0.y;
                    v1.x += d.x * x1.x; v1.y += d.y * x1.y;
                }
                *(float2*)(C + o0) = v0;
                *(float2*)(C + o1) = v1;
            }
        }
    }
}

__global__ __launch_bounds__(256, 2) void k_gemm1() {
    gemm_mma<false, true>(g_xf, g_G1f, g_Buh, nullptr, nullptr);
}
__global__ __launch_bounds__(256, 2) void k_gemm2(const float* __restrict__ D,
                                                  float* __restrict__ out) {
    gemm_mma<true, false>(g_Xf, g_G2f, out, g_xf, D);
}

// ------------------------------- scan --------------------------------------
// Pass 1: chunk sums only (read Bu fp16 once, write tiny cs).
__global__ void k_sums() {
    const int b = blockIdx.x >> 6;
    const int c = blockIdx.x & 63;
    const int p = threadIdx.x;
    const float lr = g_lam[p], li = g_lam[PP + p];
    float sr = 0.0f, si = 0.0f;
    size_t base = (size_t)(b * LEN + c * CHUNK) * N2;
#pragma unroll 4
    for (int j = 0; j < CHUNK; j++) {
        size_t o = base + (size_t)j * N2;
        float ur = __half2float(g_Buh[o + p]);
        float ui = __half2float(g_Buh[o + PP + p]);
        float nr = fmaf(lr, sr, fmaf(-li, si, ur));
        float ni = fmaf(lr, si, fmaf(li, sr, ui));
        sr = nr; si = ni;
    }
    int co = (b * NCHUNK + c) * N2;
    g_cs[co + p] = sr;
    g_cs[co + PP + p] = si;
}

// Pass 2: scan of chunk sums with multiplier lam^64 -> carries.
__global__ void k_chunkscan() {
    const int b = blockIdx.x;
    const int p = threadIdx.x;
    const float tr = g_pow[CHUNK * N2 + p], ti = g_pow[CHUNK * N2 + PP + p];
    float sr = 0.0f, si = 0.0f;
#pragma unroll 4
    for (int c = 0; c < NCHUNK; c++) {
        int o = (b * NCHUNK + c) * N2;
        g_carry[o + p] = sr;
        g_carry[o + PP + p] = si;
        float cr = g_cs[o + p], ci = g_cs[o + PP + p];
        float nr = fmaf(tr, sr, fmaf(-ti, si, cr));
        float ni = fmaf(tr, si, fmaf(ti, sr, ci));
        sr = nr; si = ni;
    }
}

// Pass 3: local scan seeded with carry, write xs directly as fp16.
__global__ void k_scanapply() {
    const int b = blockIdx.x >> 6;
    const int c = blockIdx.x & 63;
    const int p = threadIdx.x;
    const float lr = g_lam[p], li = g_lam[PP + p];
    const int co = (b * NCHUNK + c) * N2;
    float sr = (c == 0) ? 0.0f : g_carry[co + p];
    float si = (c == 0) ? 0.0f : g_carry[co + PP + p];
    size_t base = (size_t)(b * LEN + c * CHUNK) * N2;
#pragma unroll 4
    for (int j = 0; j < CHUNK; j++) {
        size_t o = base + (size_t)j * N2;
        float ur = __half2float(g_Buh[o + p]);
        float ui = __half2float(g_Buh[o + PP + p]);
        float nr = fmaf(lr, sr, fmaf(-li, si, ur));
        float ni = fmaf(lr, si, fmaf(li, sr, ui));
        g_Xf[o + p]      = __float2half_rn(nr);
        g_Xf[o + PP + p] = __float2half_rn(ni);
        sr = nr; si = ni;
    }
}

// ------------------------------ launcher -----------------------------------
extern "C" void kernel_launch(void* const* d_in, const int* in_sizes, int n_in,
                              void* d_out, int out_size) {
    (void)in_sizes; (void)n_in; (void)out_size;
    const float* x     = (const float*)d_in[0];
    const float* lre   = (const float*)d_in[1];
    const float* lim   = (const float*)d_in[2];
    const float* Bm    = (const float*)d_in[3];
    const float* Cm    = (const float*)d_in[4];
    const float* D     = (const float*)d_in[5];
    const float* lstep = (const float*)d_in[6];
    float* out = (float*)d_out;

    cudaFuncSetAttribute(k_gemm1, cudaFuncAttributeMaxDynamicSharedMemorySize, GSMEM);
    cudaFuncSetAttribute(k_gemm2, cudaFuncAttributeMaxDynamicSharedMemorySize, GSMEM);

    k_setup<<<1, 256>>>(lre, lim, lstep);
    k_fill<<<(N2 * HH + 255) / 256, 256>>>(Bm, Cm);
    k_xconv<<<(MT * N2 / 4) / 256, 256>>>(x);

    dim3 gg(NT / 128, MT / 128);  // (4, 256)
    k_gemm1<<<gg, 256, GSMEM>>>();
    k_sums<<<BSZ * NCHUNK, 256>>>();
    k_chunkscan<<<BSZ, 256>>>();
    k_scanapply<<<BSZ * NCHUNK, 256>>>();
    k_gemm2<<<gg, 256, GSMEM>>>(D, out);
}